// round 1
// baseline (speedup 1.0000x reference)
#include <cuda_runtime.h>

// ResLSTM: B=131072 sequences, 2-layer LSTM (T=5, H=32, in=62) + per-batch
// LayerNorm over (T,H) + LeakyReLU, residual, then (160 -> 3) head.
//
// Mapping: one warp processes NB=4 batch elements. Lane j owns hidden unit j
// (H == 32 == warpSize). Weights live transposed in shared memory so lane-j
// loads are conflict-free; h is broadcast across the warp with __shfl_sync.
// Each shared weight load is reused by 4 batches (16 FFMA per 4 LDS).

#define WARPS   8
#define NT      (WARPS * 32)
#define NB      4
#define B_TOTAL 131072
#define TT      5
#define HH      32
#define NF      62

// shared layout (floats)
#define OFF_WI0 0                    // 62*128
#define OFF_WH0 (OFF_WI0 + 62*128)   // 32*128
#define OFF_WI1 (OFF_WH0 + 32*128)   // 32*128
#define OFF_WH1 (OFF_WI1 + 32*128)   // 32*128
#define OFF_B0  (OFF_WH1 + 32*128)   // 128
#define OFF_B1  (OFF_B0 + 128)       // 128
#define OFF_G0  (OFF_B1 + 128)       // 160
#define OFF_BE0 (OFF_G0 + 160)       // 160
#define OFF_G1  (OFF_BE0 + 160)      // 160
#define OFF_BE1 (OFF_G1 + 160)       // 160
#define OFF_DW  (OFF_BE1 + 160)      // 480
#define OFF_DB  (OFF_DW + 480)       // 4 (3 used)
#define SMEM_FLOATS (OFF_DB + 4)
#define SMEM_BYTES  (SMEM_FLOATS * 4)

__device__ __forceinline__ float sigm(float x) {
    return __fdividef(1.0f, 1.0f + __expf(-x));
}
__device__ __forceinline__ float tanh_s(float x) {
    float ax = fabsf(x);
    float e  = __expf(-2.0f * ax);
    float t  = __fdividef(1.0f - e, 1.0f + e);
    return copysignf(t, x);
}
__device__ __forceinline__ float lrelu(float x) {
    return x > 0.0f ? x : 0.01f * x;
}

__global__ __launch_bounds__(NT) void reslstm_kernel(
    const float* __restrict__ data,
    const float* __restrict__ w_ih0, const float* __restrict__ w_hh0,
    const float* __restrict__ b_ih0, const float* __restrict__ b_hh0,
    const float* __restrict__ g0,    const float* __restrict__ be0,
    const float* __restrict__ w_ih1, const float* __restrict__ w_hh1,
    const float* __restrict__ b_ih1, const float* __restrict__ b_hh1,
    const float* __restrict__ g1,    const float* __restrict__ be1,
    const float* __restrict__ dw,    const float* __restrict__ db,
    float* __restrict__ out)
{
    extern __shared__ float sm[];
    float* sWI0 = sm + OFF_WI0;
    float* sWH0 = sm + OFF_WH0;
    float* sWI1 = sm + OFF_WI1;
    float* sWH1 = sm + OFF_WH1;
    float* sB0  = sm + OFF_B0;
    float* sB1  = sm + OFF_B1;
    float* sG0  = sm + OFF_G0;
    float* sBe0 = sm + OFF_BE0;
    float* sG1  = sm + OFF_G1;
    float* sBe1 = sm + OFF_BE1;
    float* sDW  = sm + OFF_DW;
    float* sDB  = sm + OFF_DB;

    const int tid = threadIdx.x;

    // stage weights (transposed: [k][gate_row]) so lane-j LDS is conflict-free
    for (int i = tid; i < 62*128; i += NT) {
        int n = i >> 7, gj = i & 127;
        sWI0[i] = w_ih0[gj*62 + n];
    }
    for (int i = tid; i < 32*128; i += NT) {
        int k = i >> 7, gj = i & 127;
        sWH0[i] = w_hh0[gj*32 + k];
        sWI1[i] = w_ih1[gj*32 + k];
        sWH1[i] = w_hh1[gj*32 + k];
    }
    for (int i = tid; i < 128; i += NT) {
        sB0[i] = b_ih0[i] + b_hh0[i];
        sB1[i] = b_ih1[i] + b_hh1[i];
    }
    for (int i = tid; i < 160; i += NT) {
        sG0[i] = g0[i]; sBe0[i] = be0[i];
        sG1[i] = g1[i]; sBe1[i] = be1[i];
    }
    for (int i = tid; i < 480; i += NT) sDW[i] = dw[i];
    if (tid < 3) sDB[tid] = db[tid];
    __syncthreads();

    const int lane = tid & 31;
    const int wid  = tid >> 5;
    const long long base = ((long long)blockIdx.x * WARPS + wid) * NB;
    const unsigned FULL = 0xffffffffu;

    // ---------------- layer 0 ----------------
    float h0[NB], c0[NB];
    float o0[TT][NB];   // layer-0 outputs (post-LN after LN stage)
#pragma unroll
    for (int bi = 0; bi < NB; bi++) { h0[bi] = 0.f; c0[bi] = 0.f; }

#pragma unroll
    for (int t = 0; t < TT; t++) {
        // x[t][n]: lane holds n=lane and n=lane+32 for each batch
        float xa[NB], xb[NB];
#pragma unroll
        for (int bi = 0; bi < NB; bi++) {
            const float* dp = data + (base + bi) * (NF * TT);
            xa[bi] = __ldg(dp + lane * TT + t);
            xb[bi] = (lane < NF - 32) ? __ldg(dp + (lane + 32) * TT + t) : 0.f;
        }

        float a0[NB], a1[NB], a2[NB], a3[NB];
        {
            float bi0 = sB0[lane], bi1 = sB0[32 + lane];
            float bi2 = sB0[64 + lane], bi3 = sB0[96 + lane];
#pragma unroll
            for (int bi = 0; bi < NB; bi++) { a0[bi]=bi0; a1[bi]=bi1; a2[bi]=bi2; a3[bi]=bi3; }
        }

        // input GEMV: sum over n=0..61
#pragma unroll 2
        for (int n = 0; n < NF; n++) {
            const float* wp = sWI0 + n * 128 + lane;
            float w0 = wp[0], w1 = wp[32], w2 = wp[64], w3 = wp[96];
#pragma unroll
            for (int bi = 0; bi < NB; bi++) {
                float src = (n < 32) ? xa[bi] : xb[bi];
                float xv = __shfl_sync(FULL, src, n & 31);
                a0[bi] += xv * w0; a1[bi] += xv * w1;
                a2[bi] += xv * w2; a3[bi] += xv * w3;
            }
        }
        // recurrent GEMV: sum over k=0..31
#pragma unroll 2
        for (int k = 0; k < 32; k++) {
            const float* wp = sWH0 + k * 128 + lane;
            float w0 = wp[0], w1 = wp[32], w2 = wp[64], w3 = wp[96];
#pragma unroll
            for (int bi = 0; bi < NB; bi++) {
                float hv = __shfl_sync(FULL, h0[bi], k);
                a0[bi] += hv * w0; a1[bi] += hv * w1;
                a2[bi] += hv * w2; a3[bi] += hv * w3;
            }
        }
#pragma unroll
        for (int bi = 0; bi < NB; bi++) {
            float ig = sigm(a0[bi]);
            float fg = sigm(a1[bi]);
            float gg = tanh_s(a2[bi]);
            float og = sigm(a3[bi]);
            c0[bi] = fg * c0[bi] + ig * gg;
            h0[bi] = og * tanh_s(c0[bi]);
            o0[t][bi] = h0[bi];
        }
    }

    // LayerNorm over (T,H) + LeakyReLU, per batch
#pragma unroll
    for (int bi = 0; bi < NB; bi++) {
        float s = 0.f, sq = 0.f;
#pragma unroll
        for (int t = 0; t < TT; t++) { float v = o0[t][bi]; s += v; sq += v * v; }
#pragma unroll
        for (int off = 16; off > 0; off >>= 1) {
            s  += __shfl_xor_sync(FULL, s,  off);
            sq += __shfl_xor_sync(FULL, sq, off);
        }
        float mu  = s * (1.0f / 160.0f);
        float var = sq * (1.0f / 160.0f) - mu * mu;
        float rs  = rsqrtf(var + 1e-5f);
#pragma unroll
        for (int t = 0; t < TT; t++) {
            float y = (o0[t][bi] - mu) * rs * sG0[t * 32 + lane] + sBe0[t * 32 + lane];
            o0[t][bi] = lrelu(y);
        }
    }

    // ---------------- layer 1 ----------------
    float h1[NB], c1[NB];
    float o1[TT][NB];
#pragma unroll
    for (int bi = 0; bi < NB; bi++) { h1[bi] = 0.f; c1[bi] = 0.f; }

#pragma unroll
    for (int t = 0; t < TT; t++) {
        float a0[NB], a1[NB], a2[NB], a3[NB];
        {
            float bi0 = sB1[lane], bi1 = sB1[32 + lane];
            float bi2 = sB1[64 + lane], bi3 = sB1[96 + lane];
#pragma unroll
            for (int bi = 0; bi < NB; bi++) { a0[bi]=bi0; a1[bi]=bi1; a2[bi]=bi2; a3[bi]=bi3; }
        }
#pragma unroll 2
        for (int k = 0; k < 32; k++) {
            const float* wip = sWI1 + k * 128 + lane;
            const float* whp = sWH1 + k * 128 + lane;
            float wi0 = wip[0], wi1 = wip[32], wi2 = wip[64], wi3 = wip[96];
            float wh0 = whp[0], wh1 = whp[32], wh2 = whp[64], wh3 = whp[96];
#pragma unroll
            for (int bi = 0; bi < NB; bi++) {
                float xv = __shfl_sync(FULL, o0[t][bi], k);
                float hv = __shfl_sync(FULL, h1[bi], k);
                a0[bi] += xv * wi0; a1[bi] += xv * wi1;
                a2[bi] += xv * wi2; a3[bi] += xv * wi3;
                a0[bi] += hv * wh0; a1[bi] += hv * wh1;
                a2[bi] += hv * wh2; a3[bi] += hv * wh3;
            }
        }
#pragma unroll
        for (int bi = 0; bi < NB; bi++) {
            float ig = sigm(a0[bi]);
            float fg = sigm(a1[bi]);
            float gg = tanh_s(a2[bi]);
            float og = sigm(a3[bi]);
            c1[bi] = fg * c1[bi] + ig * gg;
            h1[bi] = og * tanh_s(c1[bi]);
            o1[t][bi] = h1[bi];
        }
    }

    // LN1 + LeakyReLU, then residual with o0 (both post-LN)
#pragma unroll
    for (int bi = 0; bi < NB; bi++) {
        float s = 0.f, sq = 0.f;
#pragma unroll
        for (int t = 0; t < TT; t++) { float v = o1[t][bi]; s += v; sq += v * v; }
#pragma unroll
        for (int off = 16; off > 0; off >>= 1) {
            s  += __shfl_xor_sync(FULL, s,  off);
            sq += __shfl_xor_sync(FULL, sq, off);
        }
        float mu  = s * (1.0f / 160.0f);
        float var = sq * (1.0f / 160.0f) - mu * mu;
        float rs  = rsqrtf(var + 1e-5f);
#pragma unroll
        for (int t = 0; t < TT; t++) {
            float y = (o1[t][bi] - mu) * rs * sG1[t * 32 + lane] + sBe1[t * 32 + lane];
            o1[t][bi] = lrelu(y) + o0[t][bi];   // residual
        }
    }

    // ---------------- head: (160 -> 3) + LeakyReLU ----------------
#pragma unroll
    for (int bi = 0; bi < NB; bi++) {
        float p0 = 0.f, p1 = 0.f, p2 = 0.f;
#pragma unroll
        for (int t = 0; t < TT; t++) {
            float v = o1[t][bi];
            int idx = t * 32 + lane;
            p0 += v * sDW[idx];
            p1 += v * sDW[160 + idx];
            p2 += v * sDW[320 + idx];
        }
#pragma unroll
        for (int off = 16; off > 0; off >>= 1) {
            p0 += __shfl_xor_sync(FULL, p0, off);
            p1 += __shfl_xor_sync(FULL, p1, off);
            p2 += __shfl_xor_sync(FULL, p2, off);
        }
        if (lane < 3) {
            float pv = (lane == 0) ? p0 : ((lane == 1) ? p1 : p2);
            pv += sDB[lane];
            out[(base + bi) * 3 + lane] = lrelu(pv);
        }
    }
}

extern "C" void kernel_launch(void* const* d_in, const int* in_sizes, int n_in,
                              void* d_out, int out_size) {
    const float* data  = (const float*)d_in[0];
    const float* w_ih0 = (const float*)d_in[1];
    const float* w_hh0 = (const float*)d_in[2];
    const float* b_ih0 = (const float*)d_in[3];
    const float* b_hh0 = (const float*)d_in[4];
    const float* g0    = (const float*)d_in[5];
    const float* be0   = (const float*)d_in[6];
    const float* w_ih1 = (const float*)d_in[7];
    const float* w_hh1 = (const float*)d_in[8];
    const float* b_ih1 = (const float*)d_in[9];
    const float* b_hh1 = (const float*)d_in[10];
    const float* g1    = (const float*)d_in[11];
    const float* be1   = (const float*)d_in[12];
    const float* dw    = (const float*)d_in[13];
    const float* db    = (const float*)d_in[14];
    float* out = (float*)d_out;

    // >48KB dynamic smem requires opt-in; idempotent, capture-safe (not stream-ordered)
    cudaFuncSetAttribute(reslstm_kernel,
                         cudaFuncAttributeMaxDynamicSharedMemorySize, SMEM_BYTES);

    int grid = B_TOTAL / (WARPS * NB);   // 4096
    reslstm_kernel<<<grid, NT, SMEM_BYTES>>>(
        data, w_ih0, w_hh0, b_ih0, b_hh0, g0, be0,
        w_ih1, w_hh1, b_ih1, b_hh1, g1, be1, dw, db, out);
}

// round 2
// speedup vs baseline: 2.1166x; 2.1166x over previous
#include <cuda_runtime.h>

// ResLSTM on GB300: warp = 4 batches, lane = hidden unit j.
// All operand broadcast via per-warp smem (LDS broadcast), weights as
// float4-per-(k,lane) so one LDS.128 feeds 2 packed f32x2 gate-pair FMAs.
// Accumulators are fma.rn.f32x2 pairs: a01=(gate_i,gate_f), a23=(gate_g,gate_o).

#define WARPS   8
#define NT      (WARPS * 32)
#define NB      4
#define B_TOTAL 131072
#define TT      5
#define NF      62

typedef unsigned long long ull;

// ---- shared layout (floats) ----
#define OFF_WI0 0                     // 64*128 (rows 62,63 zero-padded)
#define OFF_WH0 (OFF_WI0 + 64*128)    // 32*128
#define OFF_W1  (OFF_WH0 + 32*128)    // 64*128 (rows 0..31 = w_ih1, 32..63 = w_hh1)
#define OFF_B0  (OFF_W1  + 64*128)    // 128  (interleaved j*4+g)
#define OFF_B1  (OFF_B0 + 128)        // 128
#define OFF_G0  (OFF_B1 + 128)        // 160
#define OFF_BE0 (OFF_G0 + 160)        // 160
#define OFF_G1  (OFF_BE0 + 160)       // 160
#define OFF_BE1 (OFF_G1 + 160)        // 160
#define OFF_DW  (OFF_BE1 + 160)       // 480
#define OFF_DB  (OFF_DW + 480)        // 4
#define OFF_SCR (OFF_DB + 4)          // per-warp scratch: 8 * 512
// per-warp scratch: [0..255] X (4 batches x 64), [256..511] OH (4 x 64: o|h)
#define SCR_PER_WARP 512
#define SMEM_FLOATS (OFF_SCR + WARPS * SCR_PER_WARP)
#define SMEM_BYTES  (SMEM_FLOATS * 4)

__device__ __forceinline__ float sigm(float x) {
    return __fdividef(1.0f, 1.0f + __expf(-x));
}
__device__ __forceinline__ float tanh_s(float x) {
    float ax = fabsf(x);
    float e  = __expf(-2.0f * ax);
    float t  = __fdividef(1.0f - e, 1.0f + e);
    return copysignf(t, x);
}
__device__ __forceinline__ float lrelu(float x) {
    return x > 0.0f ? x : 0.01f * x;
}
__device__ __forceinline__ ull pk2(float x) {           // (x, x) packed
    ull r; asm("mov.b64 %0, {%1, %2};" : "=l"(r) : "f"(x), "f"(x)); return r;
}
__device__ __forceinline__ void fma2(ull& d, ull a, ull b) {
    asm("fma.rn.f32x2 %0, %1, %2, %0;" : "+l"(d) : "l"(a), "l"(b));
}
__device__ __forceinline__ void unpk(ull v, float& lo, float& hi) {
    asm("mov.b64 {%0, %1}, %2;" : "=f"(lo), "=f"(hi) : "l"(v));
}

// one 4-wide group of a GEMV: rows r4..r4+3 of W (layout [r][lane*4+g]),
// operand vector read as broadcast float4 from per-warp scratch.
__device__ __forceinline__ void gemv_group(
    const float* __restrict__ W, const float* __restrict__ vec, int vstride,
    int r4, int lane, ull a01[NB], ull a23[NB])
{
    const ulonglong2* w = (const ulonglong2*)(W + r4 * 128) + lane;
    ulonglong2 w0 = w[0];
    ulonglong2 w1 = w[32];
    ulonglong2 w2 = w[64];
    ulonglong2 w3 = w[96];
#pragma unroll
    for (int bi = 0; bi < NB; bi++) {
        float4 xv = *(const float4*)(vec + bi * vstride + r4);
        ull xp;
        xp = pk2(xv.x); fma2(a01[bi], xp, w0.x); fma2(a23[bi], xp, w0.y);
        xp = pk2(xv.y); fma2(a01[bi], xp, w1.x); fma2(a23[bi], xp, w1.y);
        xp = pk2(xv.z); fma2(a01[bi], xp, w2.x); fma2(a23[bi], xp, w2.y);
        xp = pk2(xv.w); fma2(a01[bi], xp, w3.x); fma2(a23[bi], xp, w3.y);
    }
}

__global__ __launch_bounds__(NT, 2) void reslstm_kernel(
    const float* __restrict__ data,
    const float* __restrict__ w_ih0, const float* __restrict__ w_hh0,
    const float* __restrict__ b_ih0, const float* __restrict__ b_hh0,
    const float* __restrict__ g0,    const float* __restrict__ be0,
    const float* __restrict__ w_ih1, const float* __restrict__ w_hh1,
    const float* __restrict__ b_ih1, const float* __restrict__ b_hh1,
    const float* __restrict__ g1,    const float* __restrict__ be1,
    const float* __restrict__ dw,    const float* __restrict__ db,
    float* __restrict__ out)
{
    extern __shared__ float sm[];
    float* sWI0 = sm + OFF_WI0;
    float* sWH0 = sm + OFF_WH0;
    float* sW1  = sm + OFF_W1;
    float* sB0  = sm + OFF_B0;
    float* sB1  = sm + OFF_B1;
    float* sG0  = sm + OFF_G0;
    float* sBe0 = sm + OFF_BE0;
    float* sG1  = sm + OFF_G1;
    float* sBe1 = sm + OFF_BE1;
    float* sDW  = sm + OFF_DW;
    float* sDB  = sm + OFF_DB;

    const int tid  = threadIdx.x;
    const int lane = tid & 31;
    const int wid  = tid >> 5;

    // ---- stage weights, transposed+interleaved: [row][j*4+g] ----
    for (int i = tid; i < 64 * 128; i += NT) {
        int n = i >> 7, rem = i & 127, j = rem >> 2, g = rem & 3;
        sWI0[i] = (n < NF) ? w_ih0[(g * 32 + j) * NF + n] : 0.0f;
        int r = n;  // reuse index for W1 (64 rows)
        sW1[i] = (r < 32) ? w_ih1[(g * 32 + j) * 32 + r]
                          : w_hh1[(g * 32 + j) * 32 + (r - 32)];
    }
    for (int i = tid; i < 32 * 128; i += NT) {
        int k = i >> 7, rem = i & 127, j = rem >> 2, g = rem & 3;
        sWH0[i] = w_hh0[(g * 32 + j) * 32 + k];
    }
    for (int i = tid; i < 128; i += NT) {
        int j = i >> 2, g = i & 3;
        sB0[i] = b_ih0[g * 32 + j] + b_hh0[g * 32 + j];
        sB1[i] = b_ih1[g * 32 + j] + b_hh1[g * 32 + j];
    }
    for (int i = tid; i < 160; i += NT) {
        sG0[i] = g0[i]; sBe0[i] = be0[i];
        sG1[i] = g1[i]; sBe1[i] = be1[i];
    }
    for (int i = tid; i < 480; i += NT) sDW[i] = dw[i];
    if (tid < 3) sDB[tid] = db[tid];

    float* scrX  = sm + OFF_SCR + wid * SCR_PER_WARP;       // [bi*64 + n]
    float* scrOH = scrX + 256;                              // [bi*64 + (o:0..31 | h:32..63)]
    // zero X pad (n=62,63) and h slots (initial h0 = 0)
    if (lane < NB) {
        scrX[lane * 64 + 62] = 0.0f;
        scrX[lane * 64 + 63] = 0.0f;
    }
#pragma unroll
    for (int bi = 0; bi < NB; bi++) scrOH[bi * 64 + 32 + lane] = 0.0f;

    __syncthreads();

    const long long base = ((long long)blockIdx.x * WARPS + wid) * NB;
    const unsigned FULL = 0xffffffffu;

    // packed biases
    ulonglong2 b0p = ((const ulonglong2*)sB0)[lane];
    ulonglong2 b1p = ((const ulonglong2*)sB1)[lane];

    float h0[NB], c0[NB];
    float o0[TT][NB];
#pragma unroll
    for (int bi = 0; bi < NB; bi++) { h0[bi] = 0.f; c0[bi] = 0.f; }

    // ================= layer 0 =================
#pragma unroll
    for (int t = 0; t < TT; t++) {
        // stage x[t] for 4 batches
#pragma unroll
        for (int bi = 0; bi < NB; bi++) {
            const float* dp = data + (base + bi) * (NF * TT);
            float xa = __ldg(dp + lane * TT + t);
            scrX[bi * 64 + lane] = xa;
            if (lane < NF - 32) {
                float xb = __ldg(dp + (lane + 32) * TT + t);
                scrX[bi * 64 + 32 + lane] = xb;
            }
        }
        __syncwarp();

        ull a01[NB], a23[NB];
#pragma unroll
        for (int bi = 0; bi < NB; bi++) { a01[bi] = b0p.x; a23[bi] = b0p.y; }

#pragma unroll
        for (int r4 = 0; r4 < 64; r4 += 4)
            gemv_group(sWI0, scrX, 64, r4, lane, a01, a23);
#pragma unroll
        for (int r4 = 0; r4 < 32; r4 += 4)
            gemv_group(sWH0, scrOH + 32, 64, r4, lane, a01, a23);

        __syncwarp();
#pragma unroll
        for (int bi = 0; bi < NB; bi++) {
            float ai, af, ag, ao;
            unpk(a01[bi], ai, af);
            unpk(a23[bi], ag, ao);
            float ig = sigm(ai), fg = sigm(af);
            float gg = tanh_s(ag), og = sigm(ao);
            c0[bi] = fg * c0[bi] + ig * gg;
            h0[bi] = og * tanh_s(c0[bi]);
            o0[t][bi] = h0[bi];
            scrOH[bi * 64 + 32 + lane] = h0[bi];
        }
        __syncwarp();
    }

    // ---- LN0 + LeakyReLU ----
#pragma unroll
    for (int bi = 0; bi < NB; bi++) {
        float s = 0.f, sq = 0.f;
#pragma unroll
        for (int t = 0; t < TT; t++) { float v = o0[t][bi]; s += v; sq += v * v; }
#pragma unroll
        for (int off = 16; off > 0; off >>= 1) {
            s  += __shfl_xor_sync(FULL, s,  off);
            sq += __shfl_xor_sync(FULL, sq, off);
        }
        float mu  = s * (1.0f / 160.0f);
        float var = sq * (1.0f / 160.0f) - mu * mu;
        float rs  = rsqrtf(var + 1e-5f);
#pragma unroll
        for (int t = 0; t < TT; t++) {
            float y = (o0[t][bi] - mu) * rs * sG0[t * 32 + lane] + sBe0[t * 32 + lane];
            o0[t][bi] = lrelu(y);
        }
    }

    // re-zero h slots for layer 1
#pragma unroll
    for (int bi = 0; bi < NB; bi++) scrOH[bi * 64 + 32 + lane] = 0.0f;
    __syncwarp();

    // ================= layer 1 =================
    float h1[NB], c1[NB];
    float o1[TT][NB];
#pragma unroll
    for (int bi = 0; bi < NB; bi++) { h1[bi] = 0.f; c1[bi] = 0.f; }

#pragma unroll
    for (int t = 0; t < TT; t++) {
#pragma unroll
        for (int bi = 0; bi < NB; bi++)
            scrOH[bi * 64 + lane] = o0[t][bi];
        __syncwarp();

        ull a01[NB], a23[NB];
#pragma unroll
        for (int bi = 0; bi < NB; bi++) { a01[bi] = b1p.x; a23[bi] = b1p.y; }

        // 64-long combined GEMV: rows 0..31 = input (o0[t]), 32..63 = recurrent (h1)
#pragma unroll
        for (int r4 = 0; r4 < 64; r4 += 4)
            gemv_group(sW1, scrOH, 64, r4, lane, a01, a23);

        __syncwarp();
#pragma unroll
        for (int bi = 0; bi < NB; bi++) {
            float ai, af, ag, ao;
            unpk(a01[bi], ai, af);
            unpk(a23[bi], ag, ao);
            float ig = sigm(ai), fg = sigm(af);
            float gg = tanh_s(ag), og = sigm(ao);
            c1[bi] = fg * c1[bi] + ig * gg;
            h1[bi] = og * tanh_s(c1[bi]);
            o1[t][bi] = h1[bi];
            scrOH[bi * 64 + 32 + lane] = h1[bi];
        }
        __syncwarp();
    }

    // ---- LN1 + LeakyReLU + residual ----
#pragma unroll
    for (int bi = 0; bi < NB; bi++) {
        float s = 0.f, sq = 0.f;
#pragma unroll
        for (int t = 0; t < TT; t++) { float v = o1[t][bi]; s += v; sq += v * v; }
#pragma unroll
        for (int off = 16; off > 0; off >>= 1) {
            s  += __shfl_xor_sync(FULL, s,  off);
            sq += __shfl_xor_sync(FULL, sq, off);
        }
        float mu  = s * (1.0f / 160.0f);
        float var = sq * (1.0f / 160.0f) - mu * mu;
        float rs  = rsqrtf(var + 1e-5f);
#pragma unroll
        for (int t = 0; t < TT; t++) {
            float y = (o1[t][bi] - mu) * rs * sG1[t * 32 + lane] + sBe1[t * 32 + lane];
            o1[t][bi] = lrelu(y) + o0[t][bi];
        }
    }

    // ---- head (160 -> 3) + LeakyReLU ----
#pragma unroll
    for (int bi = 0; bi < NB; bi++) {
        float p0 = 0.f, p1 = 0.f, p2 = 0.f;
#pragma unroll
        for (int t = 0; t < TT; t++) {
            float v = o1[t][bi];
            int idx = t * 32 + lane;
            p0 += v * sDW[idx];
            p1 += v * sDW[160 + idx];
            p2 += v * sDW[320 + idx];
        }
#pragma unroll
        for (int off = 16; off > 0; off >>= 1) {
            p0 += __shfl_xor_sync(FULL, p0, off);
            p1 += __shfl_xor_sync(FULL, p1, off);
            p2 += __shfl_xor_sync(FULL, p2, off);
        }
        if (lane < 3) {
            float pv = (lane == 0) ? p0 : ((lane == 1) ? p1 : p2);
            pv += sDB[lane];
            out[(base + bi) * 3 + lane] = lrelu(pv);
        }
    }
}

extern "C" void kernel_launch(void* const* d_in, const int* in_sizes, int n_in,
                              void* d_out, int out_size) {
    const float* data  = (const float*)d_in[0];
    const float* w_ih0 = (const float*)d_in[1];
    const float* w_hh0 = (const float*)d_in[2];
    const float* b_ih0 = (const float*)d_in[3];
    const float* b_hh0 = (const float*)d_in[4];
    const float* g0    = (const float*)d_in[5];
    const float* be0   = (const float*)d_in[6];
    const float* w_ih1 = (const float*)d_in[7];
    const float* w_hh1 = (const float*)d_in[8];
    const float* b_ih1 = (const float*)d_in[9];
    const float* b_hh1 = (const float*)d_in[10];
    const float* g1    = (const float*)d_in[11];
    const float* be1   = (const float*)d_in[12];
    const float* dw    = (const float*)d_in[13];
    const float* db    = (const float*)d_in[14];
    float* out = (float*)d_out;

    cudaFuncSetAttribute(reslstm_kernel,
                         cudaFuncAttributeMaxDynamicSharedMemorySize, SMEM_BYTES);

    int grid = B_TOTAL / (WARPS * NB);   // 4096
    reslstm_kernel<<<grid, NT, SMEM_BYTES>>>(
        data, w_ih0, w_hh0, b_ih0, b_hh0, g0, be0,
        w_ih1, w_hh1, b_ih1, b_hh1, g1, be1, dw, db, out);
}